// round 4
// baseline (speedup 1.0000x reference)
#include <cuda_runtime.h>
#include <cuda_bf16.h>
#include <math.h>

// Spectral (eigendecomposition) evaluation of the reference power iteration,
// fused into a single launch (single block, 1024 threads, k = tid+1).
//
//     out = (p2/p1)^{(z-s)/2} * (2/1024) *
//           sum_{k=1}^{1023} lam_k^T sin(z k pi/1024) sin(s k pi/1024)
//     lam_k = pmid + 2 sqrt(p1 p2) cos(k pi / 1024),  z = IDX_Z = 512

struct Coef {
    double sq;     // sqrt(p1*p2)
    double d2;     // (sqrt(p1)-sqrt(p2))^2, cancellation-free
    double delta;  // (1 - pmid) - (p1 + p2)   (pmid f32 rounding residual)
    double p1d, p2d;
};

__device__ __forceinline__ Coef make_coef(float mu) {
    // Replicate the reference's float32 coefficient computation exactly.
    // DX = 2^-9 (exact) -> divisions by DX, DX^2 are exact scalings.
    float m1 = mu * 2e-6f;
    float m2 = m1 * m1 + 2e-6f;
    float a  = m2 * 262144.0f;   // m2 / DX^2
    float b  = m1 * 512.0f;      // m1 / DX
    float p1 = (a + b) * 0.5f;
    float p2 = (a - b) * 0.5f;
    float pmid = 1.0f - p1 - p2;

    Coef c;
    c.p1d = (double)p1;
    c.p2d = (double)p2;
    c.sq  = sqrt(c.p1d * c.p2d);
    double dif = c.p1d - c.p2d;                       // exact in double
    c.d2  = dif * dif / (c.p1d + c.p2d + 2.0 * c.sq); // = (sqrt(p1)-sqrt(p2))^2
    c.delta = (1.0 - (double)pmid) - (c.p1d + c.p2d); // exact in double
    return c;
}

__global__ __launch_bounds__(1024, 1)
void spectral_fused(const float* __restrict__ muP,
                    const int* __restrict__ TP,
                    const int* __restrict__ sP,
                    float* __restrict__ out) {
    __shared__ double warp_sums[32];

    const int   T = TP[0];
    const int   s = sP[0];
    const int   z = 512;  // IDX_Z
    const Coef  c = make_coef(muP[0]);

    const int k = (int)threadIdx.x + 1;   // 1..1024 (k=1024 masked below)

    double term = 0.0;
    if (k <= 1023 && s >= 1 && s <= 1023) {
        // Cheap f32 screening: eps_k = 1 - lam_k (no cancellation).
        float spf  = sinpif((float)k * (1.0f / 2048.0f));
        float epsf = (float)c.d2 + 4.0f * (float)c.sq * spf * spf;
        if (!((double)T * (double)epsf > 80.0)) {
            // Exact (double) evaluation for surviving modes.
            double sp  = sinpi((double)k / 2048.0);
            double eps = c.d2 + 4.0 * c.sq * sp * sp + c.delta;  // 1 - lam_k
            double lam = 1.0 - eps;
            double al  = fabs(lam);
            if (al > 0.0) {
                double w = (double)T * log(al);
                if (w > -745.0) {
                    double val = exp(w);
                    if (lam < 0.0 && (T & 1)) val = -val;
                    // sin(j k pi / 1024) with exact integer reduction mod 2048
                    double sz = sinpi((double)((z * k) & 2047) * (1.0 / 1024.0));
                    double ss = sinpi((double)((s * k) & 2047) * (1.0 / 1024.0));
                    term = val * sz * ss;
                }
            }
        }
    }

    // Intra-warp reduction
    #pragma unroll
    for (int o = 16; o > 0; o >>= 1)
        term += __shfl_down_sync(0xffffffffu, term, o);

    const int lane = (int)threadIdx.x & 31;
    const int wid  = (int)threadIdx.x >> 5;
    if (lane == 0) warp_sums[wid] = term;
    __syncthreads();

    // Final reduction + output on warp 0
    if (wid == 0) {
        double v = warp_sums[lane];
        #pragma unroll
        for (int o = 16; o > 0; o >>= 1)
            v += __shfl_down_sync(0xffffffffu, v, o);

        if (lane == 0) {
            // Similarity prefactor (p2/p1)^{(z-s)/2}
            double pref = exp(0.5 * (double)(z - s) * log(c.p2d / c.p1d));
            out[0] = (float)(pref * (2.0 / 1024.0) * v);
        }
    }
}

extern "C" void kernel_launch(void* const* d_in, const int* in_sizes, int n_in,
                              void* d_out, int out_size) {
    const float* mu    = (const float*)d_in[0];
    const int*   idx_T = (const int*)d_in[1];
    const int*   idx_s = (const int*)d_in[2];
    float*       out   = (float*)d_out;

    spectral_fused<<<1, 1024>>>(mu, idx_T, idx_s, out);
}

// round 5
// speedup vs baseline: 1.3936x; 1.3936x over previous
#include <cuda_runtime.h>
#include <cuda_bf16.h>
#include <math.h>

// Spectral evaluation of the reference power iteration, single fused launch.
//
//   out = (2/1024) * sum_{k=1}^{1023} exp(T*log(lam_k) + plog) * sin(z k pi/1024) * sin(s k pi/1024)
//   lam_k = pmid + 2 sqrt(p1 p2) cos(k pi/1024),  plog = (z-s)/2 * log(p2/p1),  z = 512
//
// All transcendentals are short custom double polynomials (no libdevice on the
// hot path) to minimize the FP64 dependent-latency chain, which R4 ncu showed
// to be the entire cost (20.4us kernel, all pipes ~0%).

#define TPB   512
#define KSPAN 2   // k = tid+1 and tid+1+TPB covers 1..1024

// sin(pi*y) for y in [0, 0.5]; Taylor deg-15, abs err ~6e-12.
__device__ __forceinline__ double sinpi_poly(double y) {
    double u = y * y;
    double p = -2.1915353447830217e-5;
    p = fma(p, u,  4.6630280576761255e-4);
    p = fma(p, u, -7.3704309457143510e-3);
    p = fma(p, u,  8.2145886611128228e-2);
    p = fma(p, u, -5.9926452932079210e-1);
    p = fma(p, u,  2.5501640398773455e+0);
    p = fma(p, u, -5.1677127800499700e+0);
    p = fma(p, u,  3.1415926535897931e+0);
    return p * y;
}

// sin(pi * m / 1024) for integer m in [0, 2048), exact quadrant reduction.
__device__ __forceinline__ double sinpi_m(int m) {
    double sgn = 1.0;
    if (m >= 1024) { m -= 1024; sgn = -1.0; }
    if (m > 512) m = 1024 - m;
    return sgn * sinpi_poly((double)m * (1.0 / 1024.0));
}

// exp(w) for w in ~[-200, 20]; rel err ~1e-12.
__device__ __forceinline__ double exp_custom(double w) {
    if (w < -700.0) return 0.0;
    const double L2E    = 1.4426950408889634074;
    const double LN2_HI = 6.93147180369123816490e-01;
    const double LN2_LO = 1.90821492927058770002e-10;
    int    ni = __double2int_rn(w * L2E);
    double n  = (double)ni;
    double f  = fma(-n, LN2_HI, w);
    f = fma(-n, LN2_LO, f);
    // e^f, f in [-0.347, 0.347], Horner deg-10 (trunc ~2e-13)
    double p = 2.7557319223985893e-7;
    p = fma(p, f, 2.7557319223985893e-6);
    p = fma(p, f, 2.4801587301587302e-5);
    p = fma(p, f, 1.9841269841269841e-4);
    p = fma(p, f, 1.3888888888888889e-3);
    p = fma(p, f, 8.3333333333333333e-3);
    p = fma(p, f, 4.1666666666666664e-2);
    p = fma(p, f, 1.6666666666666666e-1);
    p = fma(p, f, 5.0e-1);
    p = fma(p, f, 1.0);
    p = fma(p, f, 1.0);
    double scale = __longlong_as_double((long long)(1023 + ni) << 52);
    return p * scale;
}

__global__ __launch_bounds__(TPB, 1)
void spectral_fused(const float* __restrict__ muP,
                    const int* __restrict__ TP,
                    const int* __restrict__ sP,
                    float* __restrict__ out) {
    __shared__ double warp_sums[TPB / 32];

    const int T = TP[0];
    const int s = sP[0];
    const int z = 512;  // IDX_Z

    // ---- Coefficients: replicate the reference's float32 sequence exactly.
    // DX = 2^-9 exactly -> /DX, /DX^2 are exact scalings.
    float mu   = muP[0];
    float m1   = mu * 2e-6f;
    float m2   = m1 * m1 + 2e-6f;
    float af   = m2 * 262144.0f;   // m2 / DX^2
    float bf   = m1 * 512.0f;      // m1 / DX
    float p1   = (af + bf) * 0.5f;
    float p2   = (af - bf) * 0.5f;
    float pmid = 1.0f - p1 - p2;

    double p1d   = (double)p1;
    double p2d   = (double)p2;
    double sq    = sqrt(p1d * p2d);
    double dif   = p1d - p2d;                         // exact
    double d2    = dif * dif / (p1d + p2d + 2.0 * sq); // (sqrt p1 - sqrt p2)^2
    double delta = (1.0 - (double)pmid) - (p1d + p2d); // pmid f32 residual

    // plog = (z-s)/2 * log(p2/p1) via atanh series, |u| <= ~0.02
    double u   = (p2d - p1d) / (p2d + p1d);
    double u2  = u * u;
    double S   = u * fma(u2, fma(u2, fma(u2, 1.0 / 7.0, 0.2), 1.0 / 3.0), 1.0);
    double plog = (double)(z - s) * S;

    const float  d2f  = (float)d2;
    const float  sq4f = 4.0f * (float)sq;
    const double Td   = (double)T;
    const double sq4  = 4.0 * sq;

    double acc = 0.0;
    const bool s_ok = (s >= 1 && s <= 1023);

    #pragma unroll
    for (int i = 0; i < KSPAN; i++) {
        int k = (int)threadIdx.x + 1 + i * TPB;
        if (k > 1023 || !s_ok) continue;

        // Cheap f32 screen: eps_k = 1 - lam_k (no cancellation).
        float spf  = sinpif((float)k * (1.0f / 2048.0f));
        float epsf = fmaf(sq4f * spf, spf, d2f);
        if (Td * (double)epsf > 80.0) continue;

        // Exact eps in double (short chain).
        double sp  = sinpi_poly((double)k * (1.0 / 2048.0));
        double eps = fma(sq4 * sp, sp, d2) + delta;   // 1 - lam_k

        double term;
        if (eps <= 0.015) {
            // T*log1p(-eps) = -T*eps*(1 + eps/2 + eps^2/3 + eps^3/4 + eps^4/5)
            double q = fma(eps, fma(eps, fma(eps, fma(eps, 0.2, 0.25),
                                             1.0 / 3.0), 0.5), 1.0);
            double w = -Td * eps * q;
            term = exp_custom(w + plog);
        } else {
            // Generic fallback (never taken for T=10000 inputs): full libdevice.
            double lam = 1.0 - eps;
            double al  = fabs(lam);
            double w   = (al > 0.0) ? Td * log(al) : -1e12;
            term = (w + plog > -745.0) ? exp(w + plog) : 0.0;
            if (lam < 0.0 && (T & 1)) term = -term;
        }

        // sin(j k pi/1024) with exact integer reduction mod 2048.
        double sz = sinpi_m((z * k) & 2047);
        double ss = sinpi_m((s * k) & 2047);
        acc += term * sz * ss;
    }

    // Intra-warp reduction.
    #pragma unroll
    for (int o = 16; o > 0; o >>= 1)
        acc += __shfl_down_sync(0xffffffffu, acc, o);

    const int lane = (int)threadIdx.x & 31;
    const int wid  = (int)threadIdx.x >> 5;
    if (lane == 0) warp_sums[wid] = acc;
    __syncthreads();

    if (wid == 0) {
        double v = (lane < TPB / 32) ? warp_sums[lane] : 0.0;
        #pragma unroll
        for (int o = 8; o > 0; o >>= 1)
            v += __shfl_down_sync(0xffffffffu, v, o);
        if (lane == 0)
            out[0] = (float)(v * (2.0 / 1024.0));
    }
}

extern "C" void kernel_launch(void* const* d_in, const int* in_sizes, int n_in,
                              void* d_out, int out_size) {
    const float* mu    = (const float*)d_in[0];
    const int*   idx_T = (const int*)d_in[1];
    const int*   idx_s = (const int*)d_in[2];
    float*       out   = (float*)d_out;

    spectral_fused<<<1, TPB>>>(mu, idx_T, idx_s, out);
}

// round 6
// speedup vs baseline: 2.3310x; 1.6726x over previous
#include <cuda_runtime.h>
#include <cuda_bf16.h>
#include <math.h>

// Spectral evaluation of the reference power iteration, single launch.
//
//   out = pref * sum_{k odd} (-1)^((k-1)/2) * lam_k^T * sin(s k pi/1024)
//   lam_k = pmid + 2 sqrt(p1 p2) cos(k pi/1024)
//   pref  = (2/1024) * (p2/p1)^{(z-s)/2},  z = IDX_Z = 512
//
// Even-k modes vanish because sin(z k pi/1024) = sin(k pi/2) = 0 for even k.
// R5 ncu showed the cost was the FP64 preamble (sqrt + 2 divides) replicated
// across all 16 warps at rt~18.4 cyc/FP64-instr/SM. Here the DP constants are
// computed by ONE thread (Newton-refined f32 MUFU seeds, no DP sqrt/div), the
// prefactor by another thread concurrently, and per-mode screening is a single
// integer compare against a precomputed cutoff.

#define TPB 128

// sin(pi*y) for y in [0, 0.5]; Taylor deg-15, abs err ~6e-12.
__device__ __forceinline__ double sinpi_poly(double y) {
    double u = y * y;
    double p = -2.1915353447830217e-5;
    p = fma(p, u,  4.6630280576761255e-4);
    p = fma(p, u, -7.3704309457143510e-3);
    p = fma(p, u,  8.2145886611128228e-2);
    p = fma(p, u, -5.9926452932079210e-1);
    p = fma(p, u,  2.5501640398773455e+0);
    p = fma(p, u, -5.1677127800499700e+0);
    p = fma(p, u,  3.1415926535897931e+0);
    return p * y;
}

// sin(pi * m / 1024) for integer m in [0, 2048), exact quadrant reduction.
__device__ __forceinline__ double sinpi_m(int m) {
    double sgn = 1.0;
    if (m >= 1024) { m -= 1024; sgn = -1.0; }
    if (m > 512) m = 1024 - m;
    return sgn * sinpi_poly((double)m * (1.0 / 1024.0));
}

// exp(w) for w in ~[-700, 1]; rel err ~1e-12.
__device__ __forceinline__ double exp_custom(double w) {
    if (w < -700.0) return 0.0;
    const double L2E    = 1.4426950408889634074;
    const double LN2_HI = 6.93147180369123816490e-01;
    const double LN2_LO = 1.90821492927058770002e-10;
    int    ni = __double2int_rn(w * L2E);
    double n  = (double)ni;
    double f  = fma(-n, LN2_HI, w);
    f = fma(-n, LN2_LO, f);
    double p = 2.7557319223985893e-7;
    p = fma(p, f, 2.7557319223985893e-6);
    p = fma(p, f, 2.4801587301587302e-5);
    p = fma(p, f, 1.9841269841269841e-4);
    p = fma(p, f, 1.3888888888888889e-3);
    p = fma(p, f, 8.3333333333333333e-3);
    p = fma(p, f, 4.1666666666666664e-2);
    p = fma(p, f, 1.6666666666666666e-1);
    p = fma(p, f, 5.0e-1);
    p = fma(p, f, 1.0);
    p = fma(p, f, 1.0);
    double scale = __longlong_as_double((long long)(1023 + ni) << 52);
    return p * scale;
}

__global__ __launch_bounds__(TPB, 1)
void spectral_fused(const float* __restrict__ muP,
                    const int* __restrict__ TP,
                    const int* __restrict__ sP,
                    float* __restrict__ out) {
    __shared__ double s_sq4, s_d2, s_delta, s_pref;
    __shared__ double warp_sums[TPB / 32];

    const int tid = (int)threadIdx.x;
    const int T   = TP[0];
    const int s   = sP[0];
    const int z   = 512;  // IDX_Z

    // ---- f32 coefficients: replicate the reference's float32 sequence exactly.
    // DX = 2^-9 exactly -> /DX, /DX^2 are exact scalings.
    const float mu   = muP[0];
    const float m1   = mu * 2e-6f;
    const float m2   = m1 * m1 + 2e-6f;
    const float af   = m2 * 262144.0f;   // m2 / DX^2
    const float bf   = m1 * 512.0f;      // m1 / DX
    const float p1   = (af + bf) * 0.5f;
    const float p2   = (af - bf) * 0.5f;
    const float pmid = 1.0f - p1 - p2;

    // ---- One thread: DP constants via Newton-refined f32 seeds (no DP sqrt/div).
    if (tid == TPB - 1) {
        double p1d = (double)p1, p2d = (double)p2;
        double x  = p1d * p2d;
        double r0 = (double)rsqrtf((float)x);          // ~2e-7 rel
        double r1 = r0 * fma(-0.5 * x, r0 * r0, 1.5);  // ~1e-13 rel
        double sq = x * r1;                            // sqrt(p1*p2)
        double den = p1d + p2d + 2.0 * sq;
        double t0 = (double)__frcp_rn((float)den);
        double t1 = t0 * (2.0 - den * t0);             // 1/den, ~1e-14 rel
        double dif = p1d - p2d;                        // exact
        s_d2    = dif * dif * t1;                      // (sqrt p1 - sqrt p2)^2
        s_sq4   = 4.0 * sq;
        s_delta = (1.0 - (double)pmid) - (p1d + p2d);  // pmid f32 residual
    }
    // ---- Another thread (concurrent): prefactor exp((z-s)*atanh(u)) * 2/1024.
    if (tid == TPB - 33) {
        double p1d = (double)p1, p2d = (double)p2;
        double num = p2d - p1d, denb = p2d + p1d;
        double b0 = (double)__frcp_rn((float)denb);
        double b1 = b0 * (2.0 - denb * b0);
        double u  = num * b1;
        double u2 = u * u;
        double S  = u * fma(u2, fma(u2, fma(u2, 1.0 / 7.0, 0.2), 1.0 / 3.0), 1.0);
        s_pref = exp_custom((double)(z - s) * S) * (2.0 / 1024.0);
    }

    // ---- Per-thread f32 screening cutoff (chord bound sin(pi y) >= 2y):
    // survivors satisfy k <= 1024*sqrt((80/T - d2)/(4 sq)).
    const float sqf  = sqrtf(p1 * p2);
    const float diff = p1 - p2;
    const float d2f  = diff * diff / (p1 + p2 + 2.0f * sqf);
    const float thrf = 80.0f / (float)T;
    const float S2   = (thrf - d2f) / (4.0f * sqf);
    float kmaxf = (S2 > 0.0f) ? 1024.0f * sqrtf(S2) : 0.0f;
    const int kmax = (int)fminf(fmaxf(kmaxf * 1.0005f + 2.0f, 3.0f), 1023.0f);

    __syncthreads();

    const double sq4   = s_sq4;
    const double d2    = s_d2;
    const double delta = s_delta;
    const double Td    = (double)T;

    double acc = 0.0;
    if (s >= 1 && s <= 1023) {
        const double sgn = (tid & 1) ? -1.0 : 1.0;  // (-1)^((k-1)/2), k = 2(tid+j*TPB)+1
        for (int j = 0; j < 512 / TPB * 1 + 3; j++) {  // covers all odd k <= 1023
            int k = 2 * (tid + j * TPB) + 1;
            if (k > kmax) break;
            // eps_k = 1 - lam_k, cancellation-free.
            double sp  = sinpi_poly((double)k * (1.0 / 2048.0));
            double eps = fma(sq4 * sp, sp, d2) + delta;

            double term;
            if (eps <= 0.03) {
                // T*log1p(-eps) = -T*eps*(1 + e/2 + e^2/3 + e^3/4 + e^4/5)
                double q = fma(eps, fma(eps, fma(eps, fma(eps, 0.2, 0.25),
                                                 1.0 / 3.0), 0.5), 1.0);
                term = exp_custom(-Td * eps * q);
            } else {
                // Generic fallback (not taken for T=10000 inputs).
                double lam = 1.0 - eps;
                double al  = fabs(lam);
                double w   = (al > 0.0) ? Td * log(al) : -1e12;
                term = (w > -745.0) ? exp(w) : 0.0;
                if (lam < 0.0 && (T & 1)) term = -term;
            }
            double ss = sinpi_m((s * k) & 2047);
            acc = fma(term * ss, sgn, acc);
        }
    }

    // ---- Reduction: intra-warp, then 4 warp leaders, then warp 0.
    #pragma unroll
    for (int o = 16; o > 0; o >>= 1)
        acc += __shfl_down_sync(0xffffffffu, acc, o);

    const int lane = tid & 31;
    const int wid  = tid >> 5;
    if (lane == 0) warp_sums[wid] = acc;
    __syncthreads();

    if (wid == 0) {
        double v = (lane < TPB / 32) ? warp_sums[lane] : 0.0;
        #pragma unroll
        for (int o = (TPB / 64); o > 0; o >>= 1)
            v += __shfl_down_sync(0xffffffffu, v, o);
        if (lane == 0)
            out[0] = (float)(v * s_pref);
    }
}

extern "C" void kernel_launch(void* const* d_in, const int* in_sizes, int n_in,
                              void* d_out, int out_size) {
    const float* mu    = (const float*)d_in[0];
    const int*   idx_T = (const int*)d_in[1];
    const int*   idx_s = (const int*)d_in[2];
    float*       out   = (float*)d_out;

    spectral_fused<<<1, TPB>>>(mu, idx_T, idx_s, out);
}

// round 7
// speedup vs baseline: 3.0465x; 1.3070x over previous
#include <cuda_runtime.h>
#include <cuda_bf16.h>
#include <math.h>

// Spectral evaluation of the reference power iteration, single launch,
// FP32 hot path (FP64 only for: exact pmid residual, final accumulation).
//
//   out = pref * sum_{k odd} (-1)^((k-1)/2) * lam_k^T * sin(s k pi/1024)
//   lam_k = pmid + 2 sqrt(p1 p2) cos(k pi/1024)
//   pref  = (2/1024) * (p2/p1)^{(z-s)/2},  z = IDX_Z = 512
//
// Even-k modes vanish (sin(k pi/2) = 0). Screen: T*eps_k <= 80 with
// eps_k = 1-lam_k computed cancellation-free, so f32 eps (rel ~5e-7) gives
// |w|=T*eps <= 80 an ABSOLUTE error <= 4e-5 -> exp(w) rel err 4e-5. R6 ncu
// showed remaining cost = FP64 throughput (rt ~18.4 cyc/instr/SM) in the
// mode math and the 16-warp double reduction; both are eliminated/gated here.

#define TPB 512

__global__ __launch_bounds__(TPB, 1)
void spectral_fused(const float* __restrict__ muP,
                    const int* __restrict__ TP,
                    const int* __restrict__ sP,
                    float* __restrict__ out) {
    __shared__ double warp_sums[TPB / 32];

    const int tid = (int)threadIdx.x;
    const int T   = TP[0];
    const int s   = sP[0];

    // ---- f32 coefficients: replicate the reference's float32 sequence exactly.
    // DX = 2^-9 exactly -> /DX, /DX^2 are exact scalings.
    const float mu   = muP[0];
    const float m1   = mu * 2e-6f;
    const float m2   = m1 * m1 + 2e-6f;
    const float af   = m2 * 262144.0f;   // m2 / DX^2
    const float bf   = m1 * 512.0f;      // m1 / DX
    const float p1   = (af + bf) * 0.5f;
    const float p2   = (af - bf) * 0.5f;
    const float pmid = 1.0f - p1 - p2;

    // ---- Cancellation-free spectral constants, f32 (diff exactly rounded via double).
    const float sqf   = sqrtf(p1 * p2);                       // sqrt(p1 p2)
    const float diffc = (float)((double)p1 - (double)p2);     // p1-p2, exact->rounded
    const float d2f   = diffc * diffc / (p1 + p2 + 2.0f * sqf); // (sqrt p1 - sqrt p2)^2
    const float sq4f  = 4.0f * sqf;

    // ---- Screening cutoff (chord bound sin(pi y) >= 2y):
    // survivors satisfy k <= 1024*sqrt((80/T - d2)/(4 sq)).
    const float thr = 80.0f / (float)T;
    const float S2  = (thr - d2f) / sq4f;
    float kmaxf = (S2 > 0.0f) ? 1024.0f * sqrtf(S2) : 0.0f;
    const int kmax = (int)fminf(fmaxf(kmaxf * 1.0005f + 2.0f, 3.0f), 1023.0f);

    const int  k    = 2 * tid + 1;               // odd modes, covers 1..1023
    const bool s_ok = (s >= 1 && s <= 1023);

    double acc = 0.0;
    if (k <= kmax && s_ok) {
        // pmid f32 rounding residual, exact in double (active threads only).
        const float deltaf = (float)((1.0 - (double)pmid) - ((double)p1 + (double)p2));

        // eps_k = 1 - lam_k, cancellation-free, f32.
        float spf = sinpif((float)k * (1.0f / 2048.0f));
        float eps = fmaf(sq4f * spf, spf, d2f) + deltaf;

        float term;
        if (eps <= 0.03f) {
            // T*log1p(-eps) = -T*eps*(1 + e/2 + e^2/3 + e^3/4 + e^4/5)
            float q = fmaf(eps, fmaf(eps, fmaf(eps, fmaf(eps, 0.2f, 0.25f),
                                               0.33333334f), 0.5f), 1.0f);
            term = __expf(-(float)T * eps * q);
        } else {
            // Generic fallback (small T only; never taken for T=10000 inputs).
            double lam = 1.0 - (double)eps;
            double al  = fabs(lam);
            double w   = (al > 0.0) ? (double)T * log(al) : -1e12;
            double td  = (w > -745.0) ? exp(w) : 0.0;
            if (lam < 0.0 && (T & 1)) td = -td;
            term = (float)td;
        }

        // sin(s k pi/1024): argument is an exact multiple of 2^-10 -> sinpif
        // performs exact internal reduction.
        float ss  = sinpif((float)((s * k) & 2047) * (1.0f / 1024.0f));
        float sgn = (tid & 1) ? -1.0f : 1.0f;    // (-1)^((k-1)/2)
        acc = (double)(term * ss * sgn);
    }

    // ---- Reduction. Only warps that can hold survivors do double shfl work.
    const int  lane = tid & 31;
    const int  wid  = tid >> 5;
    const bool warp_active = s_ok && ((64 * wid + 1) <= kmax); // lane0's k

    if (warp_active) {
        #pragma unroll
        for (int o = 16; o > 0; o >>= 1)
            acc += __shfl_down_sync(0xffffffffu, acc, o);
    }
    if (lane == 0) warp_sums[wid] = warp_active ? acc : 0.0;
    __syncthreads();

    if (wid == 0) {
        double v = (lane < TPB / 32) ? warp_sums[lane] : 0.0;
        #pragma unroll
        for (int o = (TPB / 64); o > 0; o >>= 1)
            v += __shfl_down_sync(0xffffffffu, v, o);

        if (lane == 0) {
            // Prefactor (p2/p1)^{(z-s)/2} via atanh series, f32.
            float un = (float)((double)p2 - (double)p1);      // exact->rounded
            float u  = un / (p2 + p1);
            float u2 = u * u;
            float S  = u * fmaf(u2, fmaf(u2, fmaf(u2, 0.14285715f, 0.2f),
                                         0.33333334f), 1.0f);
            float pw   = (float)(512 - s) * S;                // z = 512
            float pref = __expf(pw) * (2.0f / 1024.0f);
            out[0] = (float)v * pref;
        }
    }
}

extern "C" void kernel_launch(void* const* d_in, const int* in_sizes, int n_in,
                              void* d_out, int out_size) {
    const float* mu    = (const float*)d_in[0];
    const int*   idx_T = (const int*)d_in[1];
    const int*   idx_s = (const int*)d_in[2];
    float*       out   = (float*)d_out;

    spectral_fused<<<1, TPB>>>(mu, idx_T, idx_s, out);
}